// round 4
// baseline (speedup 1.0000x reference)
#include <cuda_runtime.h>
#include <cuda_bf16.h>
#include <cstdint>

#define N_ROWS 1024
#define PPARTS 8
#define DFEAT  2048
#define DX     18432   /* 9 * 2048 */
#define MARGIN 0.3f

#define BM 128
#define BN 64
#define BK 32
#define LDT 40               /* smem row stride in bf16 elems (80B, 16B-aligned) */
#define KT (DX / BK)         /* 576 k-iterations */

// ---- device scratch (no allocations allowed) ----
__device__ __align__(16) __nv_bfloat16 g_X[N_ROWS * DX];   // ~37.7 MB
__device__ float    g_dist[N_ROWS * N_ROWS];               // 4 MB
__device__ unsigned g_mask[N_ROWS];
__device__ int      g_lab[N_ROWS];
__device__ float    g_rowloss[N_ROWS];

// ---------------- PTX helpers ----------------
__device__ __forceinline__ void cp_async16(void* smem, const void* gmem) {
    uint32_t s = (uint32_t)__cvta_generic_to_shared(smem);
    asm volatile("cp.async.cg.shared.global [%0], [%1], 16;\n" :: "r"(s), "l"(gmem));
}
__device__ __forceinline__ void cp_commit() {
    asm volatile("cp.async.commit_group;\n");
}
__device__ __forceinline__ void ldsm_x4(uint32_t* r, const void* p) {
    uint32_t addr = (uint32_t)__cvta_generic_to_shared(p);
    asm volatile("ldmatrix.sync.aligned.m8n8.x4.shared.b16 {%0,%1,%2,%3}, [%4];\n"
        : "=r"(r[0]), "=r"(r[1]), "=r"(r[2]), "=r"(r[3]) : "r"(addr));
}
__device__ __forceinline__ void mma16816(float* c, const uint32_t* a, const uint32_t* b) {
    asm volatile(
        "mma.sync.aligned.m16n8k16.row.col.f32.bf16.bf16.f32 "
        "{%0,%1,%2,%3}, {%4,%5,%6,%7}, {%8,%9}, {%0,%1,%2,%3};\n"
        : "+f"(c[0]), "+f"(c[1]), "+f"(c[2]), "+f"(c[3])
        : "r"(a[0]), "r"(a[1]), "r"(a[2]), "r"(a[3]), "r"(b[0]), "r"(b[1]));
}

// ---------------- Kernel 0: canonicalize labels (int32 OR int64 input) ----
// JAX with x64 disabled turns .astype(jnp.int64) into int32; be robust to both.
// Interpret buffer as int32 words. If int64 (little-endian, values in [0,64)),
// all odd words are 0. Random labels make misdetection probability ~(1/64)^512.
__global__ void labelfix_kernel(const int* __restrict__ w) {
    __shared__ int s_is64;
    const int tid = threadIdx.x;   // 1 block, 256 threads
    if (tid == 0) s_is64 = 1;
    __syncthreads();
    for (int i = tid; i < N_ROWS / 2; i += 256)
        if (w[2 * i + 1] != 0) s_is64 = 0;
    __syncthreads();
    const int is64 = s_is64;
    for (int i = tid; i < N_ROWS; i += 256)
        g_lab[i] = is64 ? w[2 * i] : w[i];
}

// ---------------- Kernel 1: normalize + build X (bf16) ----------------
// grid = N_ROWS * 9; block = 256. part 0 = global feat, parts 1..8 = partial.
__global__ __launch_bounds__(256) void prep_kernel(
    const float* __restrict__ gfeat, const float* __restrict__ pfeat,
    const float* __restrict__ plab)
{
    const int row  = blockIdx.x / 9;
    const int part = blockIdx.x % 9;
    const int tid  = threadIdx.x;

    const float* src = (part == 0) ? (gfeat + (size_t)row * DFEAT)
                                   : (pfeat + ((size_t)row * PPARTS + (part - 1)) * DFEAT);
    const float4* s4 = (const float4*)src;

    float ss = 0.0f;
    #pragma unroll
    for (int i = tid; i < DFEAT / 4; i += 256) {
        float4 v = s4[i];
        ss += v.x * v.x + v.y * v.y + v.z * v.z + v.w * v.w;
    }
    #pragma unroll
    for (int o = 16; o > 0; o >>= 1) ss += __shfl_xor_sync(0xFFFFFFFFu, ss, o);

    __shared__ float wss[8];
    if ((tid & 31) == 0) wss[tid >> 5] = ss;
    __syncthreads();
    float tot = wss[0] + wss[1] + wss[2] + wss[3] + wss[4] + wss[5] + wss[6] + wss[7];

    float scale = 1.0f / (sqrtf(tot) + 1e-12f);
    if (part > 0) scale *= plab[row * PPARTS + (part - 1)];   // 0.0 or 1.0

    __nv_bfloat16* dst = g_X + (size_t)row * DX + part * DFEAT;
    __nv_bfloat162* d2 = (__nv_bfloat162*)dst;
    #pragma unroll
    for (int i = tid; i < DFEAT / 4; i += 256) {
        float4 v = s4[i];
        __nv_bfloat162 lo, hi;
        lo.x = __float2bfloat16(v.x * scale);
        lo.y = __float2bfloat16(v.y * scale);
        hi.x = __float2bfloat16(v.z * scale);
        hi.y = __float2bfloat16(v.w * scale);
        d2[2 * i]     = lo;
        d2[2 * i + 1] = hi;
    }
}

// ---------------- Kernel 2: pack part-label bitmasks ----------------
__global__ void packmask_kernel(const float* __restrict__ plab) {
    int i = blockIdx.x * blockDim.x + threadIdx.x;
    if (i < N_ROWS) {
        unsigned m = 0;
        #pragma unroll
        for (int p = 0; p < PPARTS; ++p)
            if (plab[i * PPARTS + p] > 0.5f) m |= (1u << p);
        g_mask[i] = m;
    }
}

// ---------------- Kernel 3: S = X X^T + fused dist epilogue ----------------
__device__ __forceinline__ void gemm_prefetch(
    int tid, int bm, int bn, int kt, __nv_bfloat16* Asb, __nv_bfloat16* Bsb)
{
    const int k0 = kt * BK;
    #pragma unroll
    for (int j = 0; j < 2; ++j) {
        int c  = tid + 256 * j;
        int r  = c >> 2;
        int c8 = (c & 3) * 8;
        cp_async16(&Asb[r * LDT + c8], &g_X[(size_t)(bm + r) * DX + k0 + c8]);
    }
    {
        int r  = tid >> 2;
        int c8 = (tid & 3) * 8;
        cp_async16(&Bsb[r * LDT + c8], &g_X[(size_t)(bn + r) * DX + k0 + c8]);
    }
}

__global__ __launch_bounds__(256) void gemm_kernel() {
    __shared__ __align__(16) __nv_bfloat16 As[2][BM * LDT];
    __shared__ __align__(16) __nv_bfloat16 Bs[2][BN * LDT];
    __shared__ unsigned msA[BM];
    __shared__ unsigned msB[BN];

    const int tid  = threadIdx.x;
    const int bm   = blockIdx.y * BM;
    const int bn   = blockIdx.x * BN;
    const int warp = tid >> 5, lane = tid & 31;
    const int wm   = (warp & 3) * 32;     // 4 warps along M
    const int wn   = (warp >> 2) * 32;    // 2 warps along N

    if (tid < BM) msA[tid] = g_mask[bm + tid];
    if (tid < BN) msB[tid] = g_mask[bn + tid];

    float acc[2][4][4];
    #pragma unroll
    for (int mf = 0; mf < 2; ++mf)
        #pragma unroll
        for (int nf = 0; nf < 4; ++nf)
            #pragma unroll
            for (int e = 0; e < 4; ++e) acc[mf][nf][e] = 0.0f;

    gemm_prefetch(tid, bm, bn, 0, As[0], Bs[0]);
    cp_commit();

    int buf = 0;
    for (int kt = 0; kt < KT; ++kt) {
        if (kt + 1 < KT) {
            gemm_prefetch(tid, bm, bn, kt + 1, As[buf ^ 1], Bs[buf ^ 1]);
            cp_commit();
            asm volatile("cp.async.wait_group 1;\n");
        } else {
            asm volatile("cp.async.wait_group 0;\n");
        }
        __syncthreads();

        const __nv_bfloat16* Ab = As[buf];
        const __nv_bfloat16* Bb = Bs[buf];
        #pragma unroll
        for (int ks = 0; ks < 2; ++ks) {
            const int kof = ks * 16;
            uint32_t areg[2][4], breg[2][4];
            #pragma unroll
            for (int mf = 0; mf < 2; ++mf)
                ldsm_x4(areg[mf],
                        Ab + (wm + mf * 16 + (lane & 15)) * LDT + kof + ((lane >> 4) << 3));
            #pragma unroll
            for (int nq = 0; nq < 2; ++nq)
                ldsm_x4(breg[nq],
                        Bb + (wn + nq * 16 + (lane & 7) + ((lane >> 4) << 3)) * LDT
                           + kof + (((lane >> 3) & 1) << 3));
            #pragma unroll
            for (int mf = 0; mf < 2; ++mf)
                #pragma unroll
                for (int nf = 0; nf < 4; ++nf)
                    mma16816(acc[mf][nf], areg[mf], &breg[nf >> 1][(nf & 1) * 2]);
        }
        buf ^= 1;
        __syncthreads();
    }

    // Epilogue: dist = (ov+1-S) / (2*(ov+1)),  ov = popc(mask_i & mask_j)
    const int r0 = wm + (lane >> 2);
    const int c0 = wn + ((lane & 3) << 1);
    #pragma unroll
    for (int mf = 0; mf < 2; ++mf) {
        #pragma unroll
        for (int h = 0; h < 2; ++h) {
            const int lr = r0 + mf * 16 + h * 8;
            const unsigned mi = msA[lr];
            float* drow = g_dist + (size_t)(bm + lr) * N_ROWS + bn;
            #pragma unroll
            for (int nf = 0; nf < 4; ++nf) {
                #pragma unroll
                for (int e = 0; e < 2; ++e) {
                    const int lc = c0 + nf * 8 + e;
                    const float ovp1 = (float)__popc(mi & msB[lc]) + 1.0f;
                    const float S = acc[mf][nf][h * 2 + e];
                    drow[lc] = (ovp1 - S) * (0.5f / ovp1);
                }
            }
        }
    }
}

// ---------------- Kernel 4: hard pos/neg mining per row ----------------
__global__ __launch_bounds__(256) void mine_kernel() {
    __shared__ int   sl[N_ROWS];
    __shared__ float sap[256], san[256];
    const int tid = threadIdx.x;
    const int i   = blockIdx.x;

    for (int j = tid; j < N_ROWS; j += 256) sl[j] = g_lab[j];
    __syncthreads();

    const int li = sl[i];
    float ap = -1e30f, an = 1e30f;
    const float* drow = g_dist + (size_t)i * N_ROWS;
    for (int j = tid; j < N_ROWS; j += 256) {
        float dv = drow[j];
        if (sl[j] == li) ap = fmaxf(ap, dv);
        else             an = fminf(an, dv);
    }
    sap[tid] = ap; san[tid] = an;
    __syncthreads();
    #pragma unroll
    for (int s = 128; s > 0; s >>= 1) {
        if (tid < s) {
            sap[tid] = fmaxf(sap[tid], sap[tid + s]);
            san[tid] = fminf(san[tid], san[tid + s]);
        }
        __syncthreads();
    }
    if (tid == 0)
        g_rowloss[i] = fmaxf(0.0f, sap[0] - san[0] + MARGIN);
}

// ---------------- Kernel 5: mean ----------------
__global__ __launch_bounds__(256) void finalize_kernel(float* __restrict__ out) {
    __shared__ float s[256];
    const int tid = threadIdx.x;
    float v = 0.0f;
    for (int j = tid; j < N_ROWS; j += 256) v += g_rowloss[j];
    s[tid] = v;
    __syncthreads();
    #pragma unroll
    for (int st = 128; st > 0; st >>= 1) {
        if (tid < st) s[tid] += s[tid + st];
        __syncthreads();
    }
    if (tid == 0) out[0] = s[0] * (1.0f / (float)N_ROWS);
}

// ---------------- launcher ----------------
extern "C" void kernel_launch(void* const* d_in, const int* in_sizes, int n_in,
                              void* d_out, int out_size) {
    const float* gfeat = (const float*)d_in[0];
    const float* pfeat = (const float*)d_in[1];
    const float* plab  = (const float*)d_in[2];
    const int*   glabw = (const int*)d_in[3];   // int32 OR int64 words; detected on device
    float*       out   = (float*)d_out;

    labelfix_kernel<<<1, 256>>>(glabw);
    prep_kernel<<<N_ROWS * 9, 256>>>(gfeat, pfeat, plab);
    packmask_kernel<<<4, 256>>>(plab);

    dim3 grid(N_ROWS / BN, N_ROWS / BM);   // (16, 8) = 128 CTAs
    gemm_kernel<<<grid, 256>>>();

    mine_kernel<<<N_ROWS, 256>>>();
    finalize_kernel<<<1, 256>>>(out);
}

// round 7
// speedup vs baseline: 2.7983x; 2.7983x over previous
#include <cuda_runtime.h>
#include <cuda_bf16.h>
#include <cstdint>

#define N_ROWS 1024
#define PPARTS 8
#define DFEAT  2048
#define DX     18432   /* 9 * 2048 */
#define MARGIN 0.3f

// ---- GEMM tiling ----
#define TB      128                 /* tile M = N */
#define BK      64                  /* k per stage (128 bytes/row = 1 SW128 atom) */
#define KSPLIT  4
#define KCHUNK  (DX / KSPLIT)       /* 4608 */
#define NT_CTA  (KCHUNK / BK)       /* 72 stages */
#define NSTAGE  3
#define TILE_BYTES  (TB * BK * 2)           /* 16384 */
#define STAGE_BYTES (2 * TILE_BYTES)        /* 32768: A then B */
#define B_OFF   TILE_BYTES
#define DYN_SMEM (NSTAGE * STAGE_BYTES)     /* 96 KB; reused as 128x132 float transpose buf */
#define N_TRI   36                  /* 8*9/2 upper-triangular tiles */
#define NBLOCKS (N_TRI * KSPLIT)    /* 144 CTAs */

// ---- device scratch ----
__device__ __align__(16) __nv_bfloat16 g_X[N_ROWS * DX];       // ~37.7 MB
__device__ __align__(16) float g_S4[KSPLIT * N_ROWS * N_ROWS]; // 16 MB partial dots
__device__ unsigned g_mask[N_ROWS];
__device__ int      g_lab[N_ROWS];
__device__ float    g_rowloss[N_ROWS];

// =================== PTX helpers ===================
__device__ __forceinline__ uint32_t smem_u32(const void* p) {
    uint32_t a;
    asm("{ .reg .u64 t; cvta.to.shared.u64 t, %1; cvt.u32.u64 %0, t; }"
        : "=r"(a) : "l"(p));
    return a;
}
__device__ __forceinline__ void cp_async16_u(uint32_t saddr, const void* g) {
    asm volatile("cp.async.cg.shared.global [%0], [%1], 16;\n" :: "r"(saddr), "l"(g));
}
__device__ __forceinline__ void ldsm_x4_u(uint32_t* r, uint32_t addr) {
    asm volatile("ldmatrix.sync.aligned.m8n8.x4.shared.b16 {%0,%1,%2,%3}, [%4];\n"
        : "=r"(r[0]), "=r"(r[1]), "=r"(r[2]), "=r"(r[3]) : "r"(addr));
}
__device__ __forceinline__ void mma16816(float* c, const uint32_t* a, const uint32_t* b) {
    asm volatile(
        "mma.sync.aligned.m16n8k16.row.col.f32.bf16.bf16.f32 "
        "{%0,%1,%2,%3}, {%4,%5,%6,%7}, {%8,%9}, {%0,%1,%2,%3};\n"
        : "+f"(c[0]), "+f"(c[1]), "+f"(c[2]), "+f"(c[3])
        : "r"(a[0]), "r"(a[1]), "r"(a[2]), "r"(a[3]), "r"(b[0]), "r"(b[1]));
}
// SW128 swizzle on byte offset within a tile (rows are exactly 128 B)
__device__ __forceinline__ uint32_t swz(uint32_t off) {
    return off ^ ((off >> 3) & 0x70);
}

// ================= Kernel 0: canonicalize labels (int32 OR int64 input) ======
__global__ void labelfix_kernel(const int* __restrict__ w) {
    __shared__ int s_is64;
    const int tid = threadIdx.x;
    if (tid == 0) s_is64 = 1;
    __syncthreads();
    for (int i = tid; i < N_ROWS / 2; i += 256)
        if (w[2 * i + 1] != 0) s_is64 = 0;
    __syncthreads();
    const int is64 = s_is64;
    for (int i = tid; i < N_ROWS; i += 256)
        g_lab[i] = is64 ? w[2 * i] : w[i];
}

// ================= Kernel 1: normalize + build X (bf16) ======================
__global__ __launch_bounds__(256) void prep_kernel(
    const float* __restrict__ gfeat, const float* __restrict__ pfeat,
    const float* __restrict__ plab)
{
    const int row  = blockIdx.x / 9;
    const int part = blockIdx.x % 9;
    const int tid  = threadIdx.x;

    const float* src = (part == 0) ? (gfeat + (size_t)row * DFEAT)
                                   : (pfeat + ((size_t)row * PPARTS + (part - 1)) * DFEAT);
    const float4* s4 = (const float4*)src;

    float ss = 0.0f;
    #pragma unroll
    for (int i = tid; i < DFEAT / 4; i += 256) {
        float4 v = s4[i];
        ss += v.x * v.x + v.y * v.y + v.z * v.z + v.w * v.w;
    }
    #pragma unroll
    for (int o = 16; o > 0; o >>= 1) ss += __shfl_xor_sync(0xFFFFFFFFu, ss, o);

    __shared__ float wss[8];
    if ((tid & 31) == 0) wss[tid >> 5] = ss;
    __syncthreads();
    float tot = wss[0] + wss[1] + wss[2] + wss[3] + wss[4] + wss[5] + wss[6] + wss[7];

    float scale = 1.0f / (sqrtf(tot) + 1e-12f);
    if (part > 0) scale *= plab[row * PPARTS + (part - 1)];   // 0.0 or 1.0

    __nv_bfloat16* dst = g_X + (size_t)row * DX + part * DFEAT;
    __nv_bfloat162* d2 = (__nv_bfloat162*)dst;
    #pragma unroll
    for (int i = tid; i < DFEAT / 4; i += 256) {
        float4 v = s4[i];
        __nv_bfloat162 lo, hi;
        lo.x = __float2bfloat16(v.x * scale);
        lo.y = __float2bfloat16(v.y * scale);
        hi.x = __float2bfloat16(v.z * scale);
        hi.y = __float2bfloat16(v.w * scale);
        d2[2 * i]     = lo;
        d2[2 * i + 1] = hi;
    }
}

// ================= Kernel 2: pack part-label bitmasks ========================
__global__ void packmask_kernel(const float* __restrict__ plab) {
    int i = blockIdx.x * blockDim.x + threadIdx.x;
    if (i < N_ROWS) {
        unsigned m = 0;
        #pragma unroll
        for (int p = 0; p < PPARTS; ++p)
            if (plab[i * PPARTS + p] > 0.5f) m |= (1u << p);
        g_mask[i] = m;
    }
}

// ================= Kernel 3: HMMA GEMM, triangular + 4-way K-split ===========
// blockIdx.x = tri_tile * KSPLIT + split. Computes raw S partial for one
// 128x128 tile over K-chunk; writes tile and its mirror into g_S4[split].
extern __shared__ char dynsmem[];

__device__ __forceinline__ void fill_stage(uint32_t sbase, int stage,
                                           int bm, int bn, int k0, int tid) {
    const uint32_t ab = sbase + stage * STAGE_BYTES;
    const uint32_t bb = ab + B_OFF;
    // A tile: 128 rows x 128 B = 1024 16B-chunks; 512 threads -> 2 each
    #pragma unroll
    for (int j = 0; j < 2; ++j) {
        int id = tid + 512 * j;
        int r  = id >> 3;
        int ce = (id & 7) * 8;                       // elem col (x8 bf16 = 16B)
        cp_async16_u(ab + swz(r * 128 + ce * 2), &g_X[(size_t)(bm + r) * DX + k0 + ce]);
    }
    #pragma unroll
    for (int j = 0; j < 2; ++j) {
        int id = tid + 512 * j;
        int r  = id >> 3;
        int ce = (id & 7) * 8;
        cp_async16_u(bb + swz(r * 128 + ce * 2), &g_X[(size_t)(bn + r) * DX + k0 + ce]);
    }
    asm volatile("cp.async.commit_group;\n");
}

__global__ __launch_bounds__(512, 1) void gemm_kernel() {
    const int tid  = threadIdx.x;
    const int wid  = tid >> 5;
    const int lane = tid & 31;

    // decode (tri tile, split)
    int blk = blockIdx.x;
    const int split = blk % KSPLIT;
    int b = blk / KSPLIT, ti = 0;
    while (b >= 8 - ti) { b -= 8 - ti; ++ti; }
    const int tj = ti + b;
    const int bm = ti * TB, bn = tj * TB;
    const int kbase = split * KCHUNK;

    const uint32_t sbase = smem_u32(dynsmem);   // dyn smem is 1024-aligned at base

    // 16 warps: 4x4 grid of 32x32 warp tiles
    const int wm = (wid & 3) * 32;
    const int wn = (wid >> 2) * 32;

    float acc[2][4][4];
    #pragma unroll
    for (int mf = 0; mf < 2; ++mf)
        #pragma unroll
        for (int nf = 0; nf < 4; ++nf)
            #pragma unroll
            for (int e = 0; e < 4; ++e) acc[mf][nf][e] = 0.0f;

    fill_stage(sbase, 0, bm, bn, kbase, tid);
    fill_stage(sbase, 1, bm, bn, kbase + BK, tid);

    for (int kt = 0; kt < NT_CTA; ++kt) {
        if (kt == NT_CTA - 1) asm volatile("cp.async.wait_group 0;\n");
        else                  asm volatile("cp.async.wait_group 1;\n");
        __syncthreads();

        if (kt + 2 < NT_CTA)
            fill_stage(sbase, (kt + 2) % NSTAGE, bm, bn, kbase + (kt + 2) * BK, tid);

        const uint32_t ab = sbase + (kt % NSTAGE) * STAGE_BYTES;
        const uint32_t bb = ab + B_OFF;
        #pragma unroll
        for (int ks = 0; ks < 4; ++ks) {
            uint32_t areg[2][4], breg[2][4];
            #pragma unroll
            for (int mf = 0; mf < 2; ++mf) {
                const uint32_t row  = wm + mf * 16 + (lane & 15);
                const uint32_t colb = ks * 32 + ((lane >> 4) << 4);
                ldsm_x4_u(areg[mf], ab + swz(row * 128 + colb));
            }
            #pragma unroll
            for (int nq = 0; nq < 2; ++nq) {
                const uint32_t row  = wn + nq * 16 + (lane & 7) + ((lane >> 4) << 3);
                const uint32_t colb = ks * 32 + (((lane >> 3) & 1) << 4);
                ldsm_x4_u(breg[nq], bb + swz(row * 128 + colb));
            }
            #pragma unroll
            for (int mf = 0; mf < 2; ++mf)
                #pragma unroll
                for (int nf = 0; nf < 4; ++nf)
                    mma16816(acc[mf][nf], areg[mf], &breg[nf >> 1][(nf & 1) * 2]);
        }
    }
    __syncthreads();   // all reads of smem stages done; reuse as transpose buffer

    // ---- stage acc into smem (stride 132 floats keeps 16B row alignment) ----
    float* Ds = (float*)dynsmem;
    const int r0 = wm + (lane >> 2);
    const int c0 = wn + ((lane & 3) << 1);
    #pragma unroll
    for (int mf = 0; mf < 2; ++mf)
        #pragma unroll
        for (int h = 0; h < 2; ++h) {
            const int r = r0 + mf * 16 + h * 8;
            #pragma unroll
            for (int nf = 0; nf < 4; ++nf) {
                #pragma unroll
                for (int e = 0; e < 2; ++e)
                    Ds[r * 132 + c0 + nf * 8 + e] = acc[mf][nf][h * 2 + e];
            }
        }
    __syncthreads();

    float* Sout = g_S4 + ((size_t)split << 20);
    // normal orientation, coalesced float4
    #pragma unroll
    for (int it = 0; it < 8; ++it) {
        const int vid = it * 512 + tid;
        const int r = vid >> 5, c4 = (vid & 31) * 4;
        float4 v = *(const float4*)&Ds[r * 132 + c4];
        *(float4*)&Sout[(size_t)(bm + r) * N_ROWS + bn + c4] = v;
    }
    if (ti != tj) {
        #pragma unroll
        for (int it = 0; it < 8; ++it) {
            const int vid = it * 512 + tid;
            const int c = vid >> 5, r4 = (vid & 31) * 4;
            float4 v;
            v.x = Ds[(r4 + 0) * 132 + c];
            v.y = Ds[(r4 + 1) * 132 + c];
            v.z = Ds[(r4 + 2) * 132 + c];
            v.w = Ds[(r4 + 3) * 132 + c];
            *(float4*)&Sout[(size_t)(bn + c) * N_ROWS + bm + r4] = v;
        }
    }
}

// ========= Kernel 4: combine partials + dist + hard mining (fused) ===========
__global__ __launch_bounds__(256) void mine_kernel() {
    __shared__ int      sl[N_ROWS];
    __shared__ unsigned smk[N_ROWS];
    __shared__ float    sap[8], san[8];
    const int tid = threadIdx.x;
    const int i   = blockIdx.x;

    for (int j = tid; j < N_ROWS; j += 256) { sl[j] = g_lab[j]; smk[j] = g_mask[j]; }
    __syncthreads();

    const int      li = sl[i];
    const unsigned mi = smk[i];
    const size_t   ro = (size_t)i * N_ROWS;

    const int j0 = tid * 4;           // 256 threads x 4 = 1024 columns
    float4 a = *(const float4*)&g_S4[(0u << 20) + ro + j0];
    float4 b = *(const float4*)&g_S4[(1u << 20) + ro + j0];
    float4 c = *(const float4*)&g_S4[(2u << 20) + ro + j0];
    float4 d = *(const float4*)&g_S4[(3u << 20) + ro + j0];
    float S[4] = { a.x + b.x + c.x + d.x, a.y + b.y + c.y + d.y,
                   a.z + b.z + c.z + d.z, a.w + b.w + c.w + d.w };

    float ap = -1e30f, an = 1e30f;
    #pragma unroll
    for (int e = 0; e < 4; ++e) {
        const int j = j0 + e;
        const float ovp1 = (float)__popc(mi & smk[j]) + 1.0f;
        const float dv = (ovp1 - S[e]) * (0.5f / ovp1);
        if (sl[j] == li) ap = fmaxf(ap, dv);
        else             an = fminf(an, dv);
    }
    #pragma unroll
    for (int o = 16; o > 0; o >>= 1) {
        ap = fmaxf(ap, __shfl_xor_sync(0xFFFFFFFFu, ap, o));
        an = fminf(an, __shfl_xor_sync(0xFFFFFFFFu, an, o));
    }
    if ((tid & 31) == 0) { sap[tid >> 5] = ap; san[tid >> 5] = an; }
    __syncthreads();
    if (tid == 0) {
        float fap = sap[0], fan = san[0];
        #pragma unroll
        for (int w = 1; w < 8; ++w) {
            fap = fmaxf(fap, sap[w]);
            fan = fminf(fan, san[w]);
        }
        g_rowloss[i] = fmaxf(0.0f, fap - fan + MARGIN);
    }
}

// ================= Kernel 5: mean ============================================
__global__ __launch_bounds__(256) void finalize_kernel(float* __restrict__ out) {
    __shared__ float s[256];
    const int tid = threadIdx.x;
    float v = 0.0f;
    for (int j = tid; j < N_ROWS; j += 256) v += g_rowloss[j];
    s[tid] = v;
    __syncthreads();
    #pragma unroll
    for (int st = 128; st > 0; st >>= 1) {
        if (tid < st) s[tid] += s[tid + st];
        __syncthreads();
    }
    if (tid == 0) out[0] = s[0] * (1.0f / (float)N_ROWS);
}

// ================= launcher ==================================================
extern "C" void kernel_launch(void* const* d_in, const int* in_sizes, int n_in,
                              void* d_out, int out_size) {
    const float* gfeat = (const float*)d_in[0];
    const float* pfeat = (const float*)d_in[1];
    const float* plab  = (const float*)d_in[2];
    const int*   glabw = (const int*)d_in[3];   // int32 OR int64 words; detected on device
    float*       out   = (float*)d_out;

    static int cfg_done = 0;
    if (!cfg_done) {
        cudaFuncSetAttribute(gemm_kernel,
                             cudaFuncAttributeMaxDynamicSharedMemorySize, DYN_SMEM);
        cfg_done = 1;
    }

    labelfix_kernel<<<1, 256>>>(glabw);
    prep_kernel<<<N_ROWS * 9, 256>>>(gfeat, pfeat, plab);
    packmask_kernel<<<4, 256>>>(plab);

    gemm_kernel<<<NBLOCKS, 512, DYN_SMEM>>>();

    mine_kernel<<<N_ROWS, 256>>>();
    finalize_kernel<<<1, 256>>>(out);
}

// round 8
// speedup vs baseline: 3.0416x; 1.0869x over previous
#include <cuda_runtime.h>
#include <cuda_bf16.h>
#include <cstdint>

#define N_ROWS 1024
#define PPARTS 8
#define DFEAT  2048
#define DX     18432   /* 9 * 2048 */
#define MARGIN 0.3f

// ---- GEMM tiling ----
#define TB      128                 /* tile M = N */
#define BK      128                 /* k per stage: 2 x 64-elem chunks (128B rows) */
#define KSPLIT  4
#define KCHUNK  (DX / KSPLIT)       /* 4608 */
#define NT_CTA  (KCHUNK / BK)       /* 36 stages */
#define NSTAGE  3
#define CHUNK_BYTES 16384                   /* 128 rows x 128 B */
#define TILE_BYTES  (2 * CHUNK_BYTES)       /* 32768 per matrix per stage */
#define STAGE_BYTES (2 * TILE_BYTES)        /* 65536: A then B */
#define B_OFF   TILE_BYTES
#define DYN_SMEM (NSTAGE * STAGE_BYTES)     /* 192 KB */
#define N_TRI   36                  /* 8*9/2 upper-triangular tiles */
#define NBLOCKS (N_TRI * KSPLIT)    /* 144 CTAs */

// ---- device scratch ----
__device__ __align__(16) __nv_bfloat16 g_X[N_ROWS * DX];       // ~37.7 MB
__device__ __align__(16) float g_S4[KSPLIT * N_ROWS * N_ROWS]; // 16 MB partial dots
__device__ unsigned g_mask[N_ROWS];
__device__ int      g_lab[N_ROWS];
__device__ float    g_rowloss[N_ROWS];

// =================== PTX helpers ===================
__device__ __forceinline__ uint32_t smem_u32(const void* p) {
    uint32_t a;
    asm("{ .reg .u64 t; cvta.to.shared.u64 t, %1; cvt.u32.u64 %0, t; }"
        : "=r"(a) : "l"(p));
    return a;
}
__device__ __forceinline__ void cp_async16_u(uint32_t saddr, const void* g) {
    asm volatile("cp.async.cg.shared.global [%0], [%1], 16;\n" :: "r"(saddr), "l"(g));
}
__device__ __forceinline__ void ldsm_x4_u(uint32_t* r, uint32_t addr) {
    asm volatile("ldmatrix.sync.aligned.m8n8.x4.shared.b16 {%0,%1,%2,%3}, [%4];\n"
        : "=r"(r[0]), "=r"(r[1]), "=r"(r[2]), "=r"(r[3]) : "r"(addr));
}
__device__ __forceinline__ void mma16816(float* c, const uint32_t* a, const uint32_t* b) {
    asm volatile(
        "mma.sync.aligned.m16n8k16.row.col.f32.bf16.bf16.f32 "
        "{%0,%1,%2,%3}, {%4,%5,%6,%7}, {%8,%9}, {%0,%1,%2,%3};\n"
        : "+f"(c[0]), "+f"(c[1]), "+f"(c[2]), "+f"(c[3])
        : "r"(a[0]), "r"(a[1]), "r"(a[2]), "r"(a[3]), "r"(b[0]), "r"(b[1]));
}
// SW128 swizzle on byte offset within a 128B-row chunk
__device__ __forceinline__ uint32_t swz(uint32_t off) {
    return off ^ ((off >> 3) & 0x70);
}

// ================= Kernel 0: canonicalize labels (int32 OR int64 input) ======
__global__ void labelfix_kernel(const int* __restrict__ w) {
    __shared__ int s_is64;
    const int tid = threadIdx.x;
    if (tid == 0) s_is64 = 1;
    __syncthreads();
    for (int i = tid; i < N_ROWS / 2; i += 256)
        if (w[2 * i + 1] != 0) s_is64 = 0;
    __syncthreads();
    const int is64 = s_is64;
    for (int i = tid; i < N_ROWS; i += 256)
        g_lab[i] = is64 ? w[2 * i] : w[i];
}

// ================= Kernel 1: normalize + build X (bf16), register-resident ===
__global__ __launch_bounds__(256) void prep_kernel(
    const float* __restrict__ gfeat, const float* __restrict__ pfeat,
    const float* __restrict__ plab)
{
    const int row  = blockIdx.x / 9;
    const int part = blockIdx.x % 9;
    const int tid  = threadIdx.x;

    const float* src = (part == 0) ? (gfeat + (size_t)row * DFEAT)
                                   : (pfeat + ((size_t)row * PPARTS + (part - 1)) * DFEAT);
    const float4* s4 = (const float4*)src;

    // single global read pass: 2 float4 per thread held in registers
    float4 v0 = s4[tid];
    float4 v1 = s4[tid + 256];

    float ss = v0.x * v0.x + v0.y * v0.y + v0.z * v0.z + v0.w * v0.w
             + v1.x * v1.x + v1.y * v1.y + v1.z * v1.z + v1.w * v1.w;
    #pragma unroll
    for (int o = 16; o > 0; o >>= 1) ss += __shfl_xor_sync(0xFFFFFFFFu, ss, o);

    __shared__ float wss[8];
    if ((tid & 31) == 0) wss[tid >> 5] = ss;
    __syncthreads();
    float tot = wss[0] + wss[1] + wss[2] + wss[3] + wss[4] + wss[5] + wss[6] + wss[7];

    float scale = 1.0f / (sqrtf(tot) + 1e-12f);
    if (part > 0) scale *= plab[row * PPARTS + (part - 1)];   // 0.0 or 1.0

    __nv_bfloat162* d2 = (__nv_bfloat162*)(g_X + (size_t)row * DX + part * DFEAT);
    __nv_bfloat162 a, b;
    a.x = __float2bfloat16(v0.x * scale); a.y = __float2bfloat16(v0.y * scale);
    b.x = __float2bfloat16(v0.z * scale); b.y = __float2bfloat16(v0.w * scale);
    d2[2 * tid]       = a;
    d2[2 * tid + 1]   = b;
    a.x = __float2bfloat16(v1.x * scale); a.y = __float2bfloat16(v1.y * scale);
    b.x = __float2bfloat16(v1.z * scale); b.y = __float2bfloat16(v1.w * scale);
    d2[2 * (tid + 256)]     = a;
    d2[2 * (tid + 256) + 1] = b;
}

// ================= Kernel 2: pack part-label bitmasks ========================
__global__ void packmask_kernel(const float* __restrict__ plab) {
    int i = blockIdx.x * blockDim.x + threadIdx.x;
    if (i < N_ROWS) {
        unsigned m = 0;
        #pragma unroll
        for (int p = 0; p < PPARTS; ++p)
            if (plab[i * PPARTS + p] > 0.5f) m |= (1u << p);
        g_mask[i] = m;
    }
}

// ================= Kernel 3: HMMA GEMM, triangular + 4-way K-split ===========
extern __shared__ char dynsmem[];

// Stage layout per matrix: [2 k-chunks][128 rows][128 B], swizzled per chunk.
__device__ __forceinline__ void fill_stage(uint32_t sbase, int stage,
                                           int bm, int bn, int k0, int tid) {
    const uint32_t ab = sbase + stage * STAGE_BYTES;
    const uint32_t bb = ab + B_OFF;
    // per matrix: 128 rows x 16 chunks of 16B = 2048; 512 threads -> 4 each
    #pragma unroll
    for (int j = 0; j < 4; ++j) {
        int id = tid + 512 * j;
        int r  = id >> 4;
        int ce = (id & 15) * 8;                       // elem col 0..120
        const uint32_t off = ((uint32_t)(ce >> 6)) * CHUNK_BYTES
                           + swz((uint32_t)(r * 128 + (ce & 63) * 2));
        cp_async16_u(ab + off, &g_X[(size_t)(bm + r) * DX + k0 + ce]);
    }
    #pragma unroll
    for (int j = 0; j < 4; ++j) {
        int id = tid + 512 * j;
        int r  = id >> 4;
        int ce = (id & 15) * 8;
        const uint32_t off = ((uint32_t)(ce >> 6)) * CHUNK_BYTES
                           + swz((uint32_t)(r * 128 + (ce & 63) * 2));
        cp_async16_u(bb + off, &g_X[(size_t)(bn + r) * DX + k0 + ce]);
    }
    asm volatile("cp.async.commit_group;\n");
}

__device__ __forceinline__ void ld_frags(uint32_t ab, uint32_t bb, int wm, int wn,
                                         int lane, int ks,
                                         uint32_t (*areg)[4], uint32_t (*breg)[4]) {
    const uint32_t colbA = (uint32_t)(ks * 32 + ((lane >> 4) << 4));
    const uint32_t colbB = (uint32_t)(ks * 32 + (((lane >> 3) & 1) << 4));
    #pragma unroll
    for (int mf = 0; mf < 2; ++mf) {
        const uint32_t row = (uint32_t)(wm + mf * 16 + (lane & 15));
        ldsm_x4_u(areg[mf], ab + (colbA >> 7) * CHUNK_BYTES
                               + swz(row * 128 + (colbA & 127)));
    }
    #pragma unroll
    for (int nq = 0; nq < 2; ++nq) {
        const uint32_t row = (uint32_t)(wn + nq * 16 + (lane & 7) + ((lane >> 4) << 3));
        ldsm_x4_u(breg[nq], bb + (colbB >> 7) * CHUNK_BYTES
                               + swz(row * 128 + (colbB & 127)));
    }
}

__global__ __launch_bounds__(512, 1) void gemm_kernel() {
    const int tid  = threadIdx.x;
    const int wid  = tid >> 5;
    const int lane = tid & 31;

    // decode (tri tile, split)
    int blk = blockIdx.x;
    const int split = blk % KSPLIT;
    int b = blk / KSPLIT, ti = 0;
    while (b >= 8 - ti) { b -= 8 - ti; ++ti; }
    const int tj = ti + b;
    const int bm = ti * TB, bn = tj * TB;
    const int kbase = split * KCHUNK;

    const uint32_t sbase = smem_u32(dynsmem);

    // 16 warps: 4x4 grid of 32x32 warp tiles
    const int wm = (wid & 3) * 32;
    const int wn = (wid >> 2) * 32;

    float acc[2][4][4];
    #pragma unroll
    for (int mf = 0; mf < 2; ++mf)
        #pragma unroll
        for (int nf = 0; nf < 4; ++nf)
            #pragma unroll
            for (int e = 0; e < 4; ++e) acc[mf][nf][e] = 0.0f;

    fill_stage(sbase, 0, bm, bn, kbase, tid);
    fill_stage(sbase, 1, bm, bn, kbase + BK, tid);

    for (int kt = 0; kt < NT_CTA; ++kt) {
        if (kt == NT_CTA - 1) asm volatile("cp.async.wait_group 0;\n");
        else                  asm volatile("cp.async.wait_group 1;\n");
        __syncthreads();

        if (kt + 2 < NT_CTA)
            fill_stage(sbase, (kt + 2) % NSTAGE, bm, bn, kbase + (kt + 2) * BK, tid);

        const uint32_t ab = sbase + (kt % NSTAGE) * STAGE_BYTES;
        const uint32_t bb = ab + B_OFF;

        // software-pipelined fragments across the 8 ks-steps
        uint32_t areg[2][2][4], breg[2][2][4];
        ld_frags(ab, bb, wm, wn, lane, 0, areg[0], breg[0]);
        #pragma unroll
        for (int ks = 0; ks < 8; ++ks) {
            const int cur = ks & 1;
            if (ks < 7)
                ld_frags(ab, bb, wm, wn, lane, ks + 1, areg[cur ^ 1], breg[cur ^ 1]);
            #pragma unroll
            for (int mf = 0; mf < 2; ++mf)
                #pragma unroll
                for (int nf = 0; nf < 4; ++nf)
                    mma16816(acc[mf][nf], areg[cur][mf],
                             &breg[cur][nf >> 1][(nf & 1) * 2]);
        }
    }
    __syncthreads();   // all smem stage reads done; reuse as transpose buffer

    // ---- stage acc into smem (stride 132 floats keeps 16B row alignment) ----
    float* Ds = (float*)dynsmem;
    const int r0 = wm + (lane >> 2);
    const int c0 = wn + ((lane & 3) << 1);
    #pragma unroll
    for (int mf = 0; mf < 2; ++mf)
        #pragma unroll
        for (int h = 0; h < 2; ++h) {
            const int r = r0 + mf * 16 + h * 8;
            #pragma unroll
            for (int nf = 0; nf < 4; ++nf) {
                #pragma unroll
                for (int e = 0; e < 2; ++e)
                    Ds[r * 132 + c0 + nf * 8 + e] = acc[mf][nf][h * 2 + e];
            }
        }
    __syncthreads();

    float* Sout = g_S4 + ((size_t)split << 20);
    #pragma unroll
    for (int it = 0; it < 8; ++it) {
        const int vid = it * 512 + tid;
        const int r = vid >> 5, c4 = (vid & 31) * 4;
        float4 v = *(const float4*)&Ds[r * 132 + c4];
        *(float4*)&Sout[(size_t)(bm + r) * N_ROWS + bn + c4] = v;
    }
    if (ti != tj) {
        #pragma unroll
        for (int it = 0; it < 8; ++it) {
            const int vid = it * 512 + tid;
            const int c = vid >> 5, r4 = (vid & 31) * 4;
            float4 v;
            v.x = Ds[(r4 + 0) * 132 + c];
            v.y = Ds[(r4 + 1) * 132 + c];
            v.z = Ds[(r4 + 2) * 132 + c];
            v.w = Ds[(r4 + 3) * 132 + c];
            *(float4*)&Sout[(size_t)(bn + c) * N_ROWS + bm + r4] = v;
        }
    }
}

// ========= Kernel 4: combine partials + dist + hard mining (fused) ===========
__global__ __launch_bounds__(256) void mine_kernel() {
    __shared__ int      sl[N_ROWS];
    __shared__ unsigned smk[N_ROWS];
    __shared__ float    sap[8], san[8];
    const int tid = threadIdx.x;
    const int i   = blockIdx.x;

    for (int j = tid; j < N_ROWS; j += 256) { sl[j] = g_lab[j]; smk[j] = g_mask[j]; }
    __syncthreads();

    const int      li = sl[i];
    const unsigned mi = smk[i];
    const size_t   ro = (size_t)i * N_ROWS;

    const int j0 = tid * 4;           // 256 threads x 4 = 1024 columns
    float4 a = *(const float4*)&g_S4[(0u << 20) + ro + j0];
    float4 b = *(const float4*)&g_S4[(1u << 20) + ro + j0];
    float4 c = *(const float4*)&g_S4[(2u << 20) + ro + j0];
    float4 d = *(const float4*)&g_S4[(3u << 20) + ro + j0];
    float S[4] = { a.x + b.x + c.x + d.x, a.y + b.y + c.y + d.y,
                   a.z + b.z + c.z + d.z, a.w + b.w + c.w + d.w };

    float ap = -1e30f, an = 1e30f;
    #pragma unroll
    for (int e = 0; e < 4; ++e) {
        const int j = j0 + e;
        const float ovp1 = (float)__popc(mi & smk[j]) + 1.0f;
        const float dv = (ovp1 - S[e]) * (0.5f / ovp1);
        if (sl[j] == li) ap = fmaxf(ap, dv);
        else             an = fminf(an, dv);
    }
    #pragma unroll
    for (int o = 16; o > 0; o >>= 1) {
        ap = fmaxf(ap, __shfl_xor_sync(0xFFFFFFFFu, ap, o));
        an = fminf(an, __shfl_xor_sync(0xFFFFFFFFu, an, o));
    }
    if ((tid & 31) == 0) { sap[tid >> 5] = ap; san[tid >> 5] = an; }
    __syncthreads();
    if (tid == 0) {
        float fap = sap[0], fan = san[0];
        #pragma unroll
        for (int w = 1; w < 8; ++w) {
            fap = fmaxf(fap, sap[w]);
            fan = fminf(fan, san[w]);
        }
        g_rowloss[i] = fmaxf(0.0f, fap - fan + MARGIN);
    }
}

// ================= Kernel 5: mean ============================================
__global__ __launch_bounds__(256) void finalize_kernel(float* __restrict__ out) {
    __shared__ float s[256];
    const int tid = threadIdx.x;
    float v = 0.0f;
    for (int j = tid; j < N_ROWS; j += 256) v += g_rowloss[j];
    s[tid] = v;
    __syncthreads();
    #pragma unroll
    for (int st = 128; st > 0; st >>= 1) {
        if (tid < st) s[tid] += s[tid + st];
        __syncthreads();
    }
    if (tid == 0) out[0] = s[0] * (1.0f / (float)N_ROWS);
}

// ================= launcher ==================================================
extern "C" void kernel_launch(void* const* d_in, const int* in_sizes, int n_in,
                              void* d_out, int out_size) {
    const float* gfeat = (const float*)d_in[0];
    const float* pfeat = (const float*)d_in[1];
    const float* plab  = (const float*)d_in[2];
    const int*   glabw = (const int*)d_in[3];   // int32 OR int64 words; detected on device
    float*       out   = (float*)d_out;

    static int cfg_done = 0;
    if (!cfg_done) {
        cudaFuncSetAttribute(gemm_kernel,
                             cudaFuncAttributeMaxDynamicSharedMemorySize, DYN_SMEM);
        cfg_done = 1;
    }

    labelfix_kernel<<<1, 256>>>(glabw);
    prep_kernel<<<N_ROWS * 9, 256>>>(gfeat, pfeat, plab);
    packmask_kernel<<<4, 256>>>(plab);

    gemm_kernel<<<NBLOCKS, 512, DYN_SMEM>>>();

    mine_kernel<<<N_ROWS, 256>>>();
    finalize_kernel<<<1, 256>>>(out);
}

// round 9
// speedup vs baseline: 3.1046x; 1.0207x over previous
#include <cuda_runtime.h>
#include <cuda_bf16.h>
#include <cstdint>

#define N_ROWS 1024
#define PPARTS 8
#define DFEAT  2048
#define DX     18432   /* 9 * 2048 */
#define MARGIN 0.3f

// ---- GEMM tiling ----
#define TB      128                 /* tile M = N */
#define BK      64                  /* k per stage (128 B rows -> SW128 swizzle) */
#define KSPLIT  8
#define KCHUNK  (DX / KSPLIT)       /* 2304 */
#define NT_CTA  (KCHUNK / BK)       /* 36 stages */
#define NSTAGE  3
#define TILE_BYTES  (TB * BK * 2)           /* 16384 */
#define STAGE_BYTES (2 * TILE_BYTES)        /* 32768: A then B */
#define B_OFF   TILE_BYTES
#define DYN_SMEM (NSTAGE * STAGE_BYTES)     /* 96 KB (also reused as epilogue buffer) */
#define N_TRI   36                  /* 8*9/2 upper-triangular tiles */
#define NBLOCKS (N_TRI * KSPLIT)    /* 288 CTAs -> 2 per SM */

// ---- device scratch ----
__device__ __align__(16) __nv_bfloat16 g_X[N_ROWS * DX];       // ~37.7 MB
__device__ __align__(16) float g_S4[KSPLIT * N_ROWS * N_ROWS]; // 32 MB partial dots
__device__ unsigned g_mask[N_ROWS];
__device__ int      g_lab[N_ROWS];
__device__ float    g_rowloss[N_ROWS];

// =================== PTX helpers ===================
__device__ __forceinline__ uint32_t smem_u32(const void* p) {
    uint32_t a;
    asm("{ .reg .u64 t; cvta.to.shared.u64 t, %1; cvt.u32.u64 %0, t; }"
        : "=r"(a) : "l"(p));
    return a;
}
__device__ __forceinline__ void cp_async16_u(uint32_t saddr, const void* g) {
    asm volatile("cp.async.cg.shared.global [%0], [%1], 16;\n" :: "r"(saddr), "l"(g));
}
__device__ __forceinline__ void ldsm_x4_u(uint32_t* r, uint32_t addr) {
    asm volatile("ldmatrix.sync.aligned.m8n8.x4.shared.b16 {%0,%1,%2,%3}, [%4];\n"
        : "=r"(r[0]), "=r"(r[1]), "=r"(r[2]), "=r"(r[3]) : "r"(addr));
}
__device__ __forceinline__ void mma16816(float* c, const uint32_t* a, const uint32_t* b) {
    asm volatile(
        "mma.sync.aligned.m16n8k16.row.col.f32.bf16.bf16.f32 "
        "{%0,%1,%2,%3}, {%4,%5,%6,%7}, {%8,%9}, {%0,%1,%2,%3};\n"
        : "+f"(c[0]), "+f"(c[1]), "+f"(c[2]), "+f"(c[3])
        : "r"(a[0]), "r"(a[1]), "r"(a[2]), "r"(a[3]), "r"(b[0]), "r"(b[1]));
}
// SW128 swizzle on byte offset within a 128B-row tile
__device__ __forceinline__ uint32_t swz(uint32_t off) {
    return off ^ ((off >> 3) & 0x70);
}

// ======== Kernel 0: labels (int32 OR int64) + part-label bitmasks ============
__global__ __launch_bounds__(1024) void meta_kernel(const int* __restrict__ w,
                                                    const float* __restrict__ plab) {
    __shared__ int s_is64;
    const int tid = threadIdx.x;   // 1 block, 1024 threads
    if (tid == 0) s_is64 = 1;
    __syncthreads();
    if (tid < N_ROWS / 2 && w[2 * tid + 1] != 0) s_is64 = 0;
    __syncthreads();
    const int is64 = s_is64;
    g_lab[tid] = is64 ? w[2 * tid] : w[tid];

    unsigned m = 0;
    #pragma unroll
    for (int p = 0; p < PPARTS; ++p)
        if (plab[tid * PPARTS + p] > 0.5f) m |= (1u << p);
    g_mask[tid] = m;
}

// ================= Kernel 1: normalize + build X (bf16), register-resident ===
__global__ __launch_bounds__(256) void prep_kernel(
    const float* __restrict__ gfeat, const float* __restrict__ pfeat,
    const float* __restrict__ plab)
{
    const int row  = blockIdx.x / 9;
    const int part = blockIdx.x % 9;
    const int tid  = threadIdx.x;

    const float* src = (part == 0) ? (gfeat + (size_t)row * DFEAT)
                                   : (pfeat + ((size_t)row * PPARTS + (part - 1)) * DFEAT);
    const float4* s4 = (const float4*)src;

    float4 v0 = s4[tid];
    float4 v1 = s4[tid + 256];

    float ss = v0.x * v0.x + v0.y * v0.y + v0.z * v0.z + v0.w * v0.w
             + v1.x * v1.x + v1.y * v1.y + v1.z * v1.z + v1.w * v1.w;
    #pragma unroll
    for (int o = 16; o > 0; o >>= 1) ss += __shfl_xor_sync(0xFFFFFFFFu, ss, o);

    __shared__ float wss[8];
    if ((tid & 31) == 0) wss[tid >> 5] = ss;
    __syncthreads();
    float tot = wss[0] + wss[1] + wss[2] + wss[3] + wss[4] + wss[5] + wss[6] + wss[7];

    float scale = 1.0f / (sqrtf(tot) + 1e-12f);
    if (part > 0) scale *= plab[row * PPARTS + (part - 1)];   // 0.0 or 1.0

    __nv_bfloat162* d2 = (__nv_bfloat162*)(g_X + (size_t)row * DX + part * DFEAT);
    __nv_bfloat162 a, b;
    a.x = __float2bfloat16(v0.x * scale); a.y = __float2bfloat16(v0.y * scale);
    b.x = __float2bfloat16(v0.z * scale); b.y = __float2bfloat16(v0.w * scale);
    d2[2 * tid]       = a;
    d2[2 * tid + 1]   = b;
    a.x = __float2bfloat16(v1.x * scale); a.y = __float2bfloat16(v1.y * scale);
    b.x = __float2bfloat16(v1.z * scale); b.y = __float2bfloat16(v1.w * scale);
    d2[2 * (tid + 256)]     = a;
    d2[2 * (tid + 256) + 1] = b;
}

// ================= Kernel 2: HMMA GEMM, triangular + 8-way K-split ===========
// 256 threads, 8 warps in a 2x4 grid of 64x32 warp tiles. 2 CTAs per SM.
extern __shared__ char dynsmem[];

__device__ __forceinline__ void fill_stage(uint32_t sbase, int stage,
                                           int bm, int bn, int k0, int tid) {
    const uint32_t ab = sbase + stage * STAGE_BYTES;
    const uint32_t bb = ab + B_OFF;
    // per matrix: 128 rows x 8 chunks of 16B = 1024; 256 threads -> 4 each
    #pragma unroll
    for (int j = 0; j < 4; ++j) {
        int id = tid + 256 * j;
        int r  = id >> 3;
        int ce = (id & 7) * 8;    // elem col 0..56
        cp_async16_u(ab + swz((uint32_t)(r * 128 + ce * 2)),
                     &g_X[(size_t)(bm + r) * DX + k0 + ce]);
    }
    #pragma unroll
    for (int j = 0; j < 4; ++j) {
        int id = tid + 256 * j;
        int r  = id >> 3;
        int ce = (id & 7) * 8;
        cp_async16_u(bb + swz((uint32_t)(r * 128 + ce * 2)),
                     &g_X[(size_t)(bn + r) * DX + k0 + ce]);
    }
    asm volatile("cp.async.commit_group;\n");
}

__device__ __forceinline__ void ld_frags(uint32_t ab, uint32_t bb, int wm, int wn,
                                         int lane, int ks,
                                         uint32_t (*areg)[4], uint32_t (*breg)[4]) {
    const uint32_t colbA = (uint32_t)(ks * 32 + ((lane >> 4) << 4));
    const uint32_t colbB = (uint32_t)(ks * 32 + (((lane >> 3) & 1) << 4));
    #pragma unroll
    for (int mf = 0; mf < 4; ++mf) {
        const uint32_t row = (uint32_t)(wm + mf * 16 + (lane & 15));
        ldsm_x4_u(areg[mf], ab + swz(row * 128 + colbA));
    }
    #pragma unroll
    for (int nq = 0; nq < 2; ++nq) {
        const uint32_t row = (uint32_t)(wn + nq * 16 + (lane & 7) + ((lane >> 4) << 3));
        ldsm_x4_u(breg[nq], bb + swz(row * 128 + colbB));
    }
}

__global__ __launch_bounds__(256, 2) void gemm_kernel() {
    const int tid  = threadIdx.x;
    const int wid  = tid >> 5;
    const int lane = tid & 31;

    // decode (tri tile, split)
    int blk = blockIdx.x;
    const int split = blk % KSPLIT;
    int b = blk / KSPLIT, ti = 0;
    while (b >= 8 - ti) { b -= 8 - ti; ++ti; }
    const int tj = ti + b;
    const int bm = ti * TB, bn = tj * TB;
    const int kbase = split * KCHUNK;

    const uint32_t sbase = smem_u32(dynsmem);

    // 8 warps: 2(M) x 4(N) grid of 64x32 warp tiles
    const int wm = (wid & 1) * 64;
    const int wn = (wid >> 1) * 32;

    float acc[4][4][4];
    #pragma unroll
    for (int mf = 0; mf < 4; ++mf)
        #pragma unroll
        for (int nf = 0; nf < 4; ++nf)
            #pragma unroll
            for (int e = 0; e < 4; ++e) acc[mf][nf][e] = 0.0f;

    fill_stage(sbase, 0, bm, bn, kbase, tid);
    fill_stage(sbase, 1, bm, bn, kbase + BK, tid);

    for (int kt = 0; kt < NT_CTA; ++kt) {
        if (kt == NT_CTA - 1) asm volatile("cp.async.wait_group 0;\n");
        else                  asm volatile("cp.async.wait_group 1;\n");
        __syncthreads();

        if (kt + 2 < NT_CTA)
            fill_stage(sbase, (kt + 2) % NSTAGE, bm, bn, kbase + (kt + 2) * BK, tid);

        const uint32_t ab = sbase + (kt % NSTAGE) * STAGE_BYTES;
        const uint32_t bb = ab + B_OFF;

        // software-pipelined fragments across the 4 ks-steps (k16 each)
        uint32_t areg[2][4][4], breg[2][2][4];
        ld_frags(ab, bb, wm, wn, lane, 0, areg[0], breg[0]);
        #pragma unroll
        for (int ks = 0; ks < 4; ++ks) {
            const int cur = ks & 1;
            if (ks < 3)
                ld_frags(ab, bb, wm, wn, lane, ks + 1, areg[cur ^ 1], breg[cur ^ 1]);
            #pragma unroll
            for (int mf = 0; mf < 4; ++mf)
                #pragma unroll
                for (int nf = 0; nf < 4; ++nf)
                    mma16816(acc[mf][nf], areg[cur][mf],
                             &breg[cur][nf >> 1][(nf & 1) * 2]);
        }
    }
    __syncthreads();   // all smem stage reads done; reuse as epilogue buffer

    // ---- stage acc into smem (stride 132 floats keeps 16B row alignment) ----
    float* Ds = (float*)dynsmem;
    const int r0 = wm + (lane >> 2);
    const int c0 = wn + ((lane & 3) << 1);
    #pragma unroll
    for (int mf = 0; mf < 4; ++mf)
        #pragma unroll
        for (int h = 0; h < 2; ++h) {
            const int r = r0 + mf * 16 + h * 8;
            #pragma unroll
            for (int nf = 0; nf < 4; ++nf) {
                #pragma unroll
                for (int e = 0; e < 2; ++e)
                    Ds[r * 132 + c0 + nf * 8 + e] = acc[mf][nf][h * 2 + e];
            }
        }
    __syncthreads();

    float* Sout = g_S4 + ((size_t)split << 20);
    #pragma unroll
    for (int it = 0; it < 16; ++it) {
        const int vid = it * 256 + tid;
        const int r = vid >> 5, c4 = (vid & 31) * 4;
        float4 v = *(const float4*)&Ds[r * 132 + c4];
        *(float4*)&Sout[(size_t)(bm + r) * N_ROWS + bn + c4] = v;
    }
    if (ti != tj) {
        #pragma unroll
        for (int it = 0; it < 16; ++it) {
            const int vid = it * 256 + tid;
            const int c = vid >> 5, r4 = (vid & 31) * 4;
            float4 v;
            v.x = Ds[(r4 + 0) * 132 + c];
            v.y = Ds[(r4 + 1) * 132 + c];
            v.z = Ds[(r4 + 2) * 132 + c];
            v.w = Ds[(r4 + 3) * 132 + c];
            *(float4*)&Sout[(size_t)(bn + c) * N_ROWS + bm + r4] = v;
        }
    }
}

// ========= Kernel 3: combine partials + dist + hard mining (fused) ===========
__global__ __launch_bounds__(256) void mine_kernel() {
    __shared__ int      sl[N_ROWS];
    __shared__ unsigned smk[N_ROWS];
    __shared__ float    sap[8], san[8];
    const int tid = threadIdx.x;
    const int i   = blockIdx.x;

    for (int j = tid; j < N_ROWS; j += 256) { sl[j] = g_lab[j]; smk[j] = g_mask[j]; }
    __syncthreads();

    const int      li = sl[i];
    const unsigned mi = smk[i];
    const size_t   ro = (size_t)i * N_ROWS;

    const int j0 = tid * 4;           // 256 threads x 4 = 1024 columns
    float S[4] = {0.f, 0.f, 0.f, 0.f};
    #pragma unroll
    for (int sp = 0; sp < KSPLIT; ++sp) {
        float4 v = *(const float4*)&g_S4[((size_t)sp << 20) + ro + j0];
        S[0] += v.x; S[1] += v.y; S[2] += v.z; S[3] += v.w;
    }

    float ap = -1e30f, an = 1e30f;
    #pragma unroll
    for (int e = 0; e < 4; ++e) {
        const int j = j0 + e;
        const float ovp1 = (float)__popc(mi & smk[j]) + 1.0f;
        const float dv = (ovp1 - S[e]) * (0.5f / ovp1);
        if (sl[j] == li) ap = fmaxf(ap, dv);
        else             an = fminf(an, dv);
    }
    #pragma unroll
    for (int o = 16; o > 0; o >>= 1) {
        ap = fmaxf(ap, __shfl_xor_sync(0xFFFFFFFFu, ap, o));
        an = fminf(an, __shfl_xor_sync(0xFFFFFFFFu, an, o));
    }
    if ((tid & 31) == 0) { sap[tid >> 5] = ap; san[tid >> 5] = an; }
    __syncthreads();
    if (tid == 0) {
        float fap = sap[0], fan = san[0];
        #pragma unroll
        for (int w = 1; w < 8; ++w) {
            fap = fmaxf(fap, sap[w]);
            fan = fminf(fan, san[w]);
        }
        g_rowloss[i] = fmaxf(0.0f, fap - fan + MARGIN);
    }
}

// ================= Kernel 4: mean ============================================
__global__ __launch_bounds__(256) void finalize_kernel(float* __restrict__ out) {
    __shared__ float s[256];
    const int tid = threadIdx.x;
    float v = 0.0f;
    for (int j = tid; j < N_ROWS; j += 256) v += g_rowloss[j];
    s[tid] = v;
    __syncthreads();
    #pragma unroll
    for (int st = 128; st > 0; st >>= 1) {
        if (tid < st) s[tid] += s[tid + st];
        __syncthreads();
    }
    if (tid == 0) out[0] = s[0] * (1.0f / (float)N_ROWS);
}

// ================= launcher ==================================================
extern "C" void kernel_launch(void* const* d_in, const int* in_sizes, int n_in,
                              void* d_out, int out_size) {
    const float* gfeat = (const float*)d_in[0];
    const float* pfeat = (const float*)d_in[1];
    const float* plab  = (const float*)d_in[2];
    const int*   glabw = (const int*)d_in[3];   // int32 OR int64 words; detected on device
    float*       out   = (float*)d_out;

    static int cfg_done = 0;
    if (!cfg_done) {
        cudaFuncSetAttribute(gemm_kernel,
                             cudaFuncAttributeMaxDynamicSharedMemorySize, DYN_SMEM);
        cfg_done = 1;
    }

    meta_kernel<<<1, 1024>>>(glabw, plab);
    prep_kernel<<<N_ROWS * 9, 256>>>(gfeat, pfeat, plab);

    gemm_kernel<<<NBLOCKS, 256, DYN_SMEM>>>();

    mine_kernel<<<N_ROWS, 256>>>();
    finalize_kernel<<<1, 256>>>(out);
}